// round 2
// baseline (speedup 1.0000x reference)
#include <cuda_runtime.h>

// FFM pairwise interactions:
//   inputs: (B=4096, N*N=400, E=64) fp32, viewed as v[b, j, i, e]
//   output: (B, 1, P=190, E) fp32, out[b, 0, p, e] = v[b, jj, ii, e] * v[b, ii, jj, e]
// Pure HBM streaming (~598 MB total); goal = saturate DRAM via ILP=4.

constexpr int N_FIELDS = 20;
constexpr int NPAIRS   = 190;   // N*(N-1)/2
constexpr int QUADS    = 16;    // float4 per 64-float row
constexpr int ILP      = 4;     // float4 per thread (64 B)

__global__ void __launch_bounds__(256)
ffm_pair_kernel(const float4* __restrict__ in, float4* __restrict__ out)
{
    int t = blockIdx.x * blockDim.x + threadIdx.x;
    int f4 = t * ILP;              // first output float4 index for this thread

    int q  = f4 & (QUADS - 1);     // 0,4,8,12 — all ILP quads in same row
    int bp = f4 >> 4;              // b * NPAIRS + p
    int p  = bp % NPAIRS;
    int b  = bp / NPAIRS;

    // Decode triu pair index p -> (i, j), i<j. <=19 iterations, amortized over
    // 4 float4s; a warp spans only 2 distinct p values.
    int i = 0, rem = p;
    #pragma unroll 1
    while (rem >= N_FIELDS - 1 - i) { rem -= N_FIELDS - 1 - i; ++i; }
    int j = i + 1 + rem;

    const long base = (long)b * (N_FIELDS * N_FIELDS) * QUADS;
    const float4* __restrict__ pa = in + base + (long)(j * N_FIELDS + i) * QUADS + q; // v[b,j,i,:]
    const float4* __restrict__ pc = in + base + (long)(i * N_FIELDS + j) * QUADS + q; // v[b,i,j,:]

    // 8 independent loads, front-batched by ptxas -> deep MLP
    float4 a0 = __ldg(pa + 0), a1 = __ldg(pa + 1), a2 = __ldg(pa + 2), a3 = __ldg(pa + 3);
    float4 c0 = __ldg(pc + 0), c1 = __ldg(pc + 1), c2 = __ldg(pc + 2), c3 = __ldg(pc + 3);

    float4 r0, r1, r2, r3;
    r0.x = a0.x * c0.x; r0.y = a0.y * c0.y; r0.z = a0.z * c0.z; r0.w = a0.w * c0.w;
    r1.x = a1.x * c1.x; r1.y = a1.y * c1.y; r1.z = a1.z * c1.z; r1.w = a1.w * c1.w;
    r2.x = a2.x * c2.x; r2.y = a2.y * c2.y; r2.z = a2.z * c2.z; r2.w = a2.w * c2.w;
    r3.x = a3.x * c3.x; r3.y = a3.y * c3.y; r3.z = a3.z * c3.z; r3.w = a3.w * c3.w;

    out[f4 + 0] = r0;
    out[f4 + 1] = r1;
    out[f4 + 2] = r2;
    out[f4 + 3] = r3;
}

extern "C" void kernel_launch(void* const* d_in, const int* in_sizes, int n_in,
                              void* d_out, int out_size)
{
    const float4* in  = (const float4*)d_in[0];
    float4*       out = (float4*)d_out;

    // total float4 outputs = out_size/4 = 4096*190*16 = 12,441,600
    int total_f4 = out_size / 4;
    int threads  = 256;
    int blocks   = (total_f4 / ILP + threads - 1) / threads;  // 12,441,600/4/256 = 12150 exact
    ffm_pair_kernel<<<blocks, threads>>>(in, out);
}

// round 3
// speedup vs baseline: 1.0064x; 1.0064x over previous
#include <cuda_runtime.h>

// FFM pairwise interactions:
//   inputs: (B=4096, 400, 64) fp32, v[b, j, i, e]
//   output: (B, 1, 190, 64) fp32, out[b,0,p,:] = v[b,jj,ii,:] * v[b,ii,jj,:]
// HBM-streaming (~598 MB). R3: coalesced grid-stride ILP=4 + constant-table
// pair decode (R2 showed consecutive-f4 ILP breaks coalescing; R1 decode loop
// burned 28% alu).

constexpr int N_FIELDS = 20;
constexpr int NPAIRS   = 190;
constexpr int QUADS    = 16;                    // float4 per 64-elem row
constexpr int ROW_F4   = N_FIELDS * N_FIELDS * QUADS;  // 6400 float4 per batch
constexpr int TOTAL_F4 = 4096 * NPAIRS * QUADS;        // 12,441,600
constexpr int ILP      = 4;
constexpr int THREADS  = 256;
constexpr int BLOCKS   = TOTAL_F4 / (THREADS * ILP);   // 12150 exact
constexpr int SPAN     = BLOCKS * THREADS;             // grid stride in f4 units

// Precomputed per-pair float4 offsets: offA[p] = (j*20+i)*16, offC[p] = (i*20+j)*16
struct PairTab { unsigned short offA[NPAIRS]; unsigned short offC[NPAIRS]; };
constexpr PairTab make_tab() {
    PairTab t{};
    int p = 0;
    for (int i = 0; i < N_FIELDS; ++i)
        for (int j = i + 1; j < N_FIELDS; ++j, ++p) {
            t.offA[p] = (unsigned short)((j * N_FIELDS + i) * QUADS);
            t.offC[p] = (unsigned short)((i * N_FIELDS + j) * QUADS);
        }
    return t;
}
__constant__ PairTab TAB = make_tab();

__global__ void __launch_bounds__(THREADS)
ffm_pair_kernel(const float4* __restrict__ in, float4* __restrict__ out)
{
    const int t0 = blockIdx.x * THREADS + threadIdx.x;

    int       idx[ILP];
    const float4* pa[ILP];
    const float4* pc[ILP];

    // Compute all addresses first (pure ALU/LDC), then batch the 8 loads.
    #pragma unroll
    for (int k = 0; k < ILP; ++k) {
        int f4 = t0 + k * SPAN;          // always < TOTAL_F4 (exact grid)
        idx[k] = f4;
        int q  = f4 & (QUADS - 1);
        int bp = f4 >> 4;
        int p  = bp % NPAIRS;            // magic-mul
        int b  = bp / NPAIRS;
        const float4* base = in + (long)b * ROW_F4 + q;
        pa[k] = base + TAB.offA[p];
        pc[k] = base + TAB.offC[p];
    }

    float4 a[ILP], c[ILP];
    #pragma unroll
    for (int k = 0; k < ILP; ++k) a[k] = __ldg(pa[k]);
    #pragma unroll
    for (int k = 0; k < ILP; ++k) c[k] = __ldg(pc[k]);

    #pragma unroll
    for (int k = 0; k < ILP; ++k) {
        float4 r;
        r.x = a[k].x * c[k].x;
        r.y = a[k].y * c[k].y;
        r.z = a[k].z * c[k].z;
        r.w = a[k].w * c[k].w;
        out[idx[k]] = r;
    }
}

extern "C" void kernel_launch(void* const* d_in, const int* in_sizes, int n_in,
                              void* d_out, int out_size)
{
    const float4* in  = (const float4*)d_in[0];
    float4*       out = (float4*)d_out;
    ffm_pair_kernel<<<BLOCKS, THREADS>>>(in, out);
}

// round 4
// speedup vs baseline: 1.0220x; 1.0155x over previous
#include <cuda_runtime.h>

// FFM pairwise interactions:
//   inputs: (B=4096, 400, 64) fp32, v[b, j, i, e]
//   output: (B, 1, 190, 64) fp32, out[b,0,p,:] = v[b,jj,ii,:] * v[b,ii,jj,:]
// Pure HBM streaming, 597 MB floor. R4: grid-stride ILP=2 + constant-table
// pair decode + streaming (evict-first) loads/stores to stop the read and
// write streams thrashing L2 (working set 797 MB >> 126 MB L2, zero reuse).

constexpr int N_FIELDS = 20;
constexpr int NPAIRS   = 190;
constexpr int QUADS    = 16;                           // float4 per 64-elem row
constexpr int ROW_F4   = N_FIELDS * N_FIELDS * QUADS;  // 6400 float4 per batch
constexpr int TOTAL_F4 = 4096 * NPAIRS * QUADS;        // 12,441,600
constexpr int ILP      = 2;
constexpr int THREADS  = 256;
constexpr int BLOCKS   = TOTAL_F4 / (THREADS * ILP);   // 24300 exact
constexpr int SPAN     = BLOCKS * THREADS;             // grid stride in f4 units

// Precomputed per-pair float4 offsets: offA[p] = (j*20+i)*16, offC[p] = (i*20+j)*16
struct PairTab { unsigned short offA[NPAIRS]; unsigned short offC[NPAIRS]; };
constexpr PairTab make_tab() {
    PairTab t{};
    int p = 0;
    for (int i = 0; i < N_FIELDS; ++i)
        for (int j = i + 1; j < N_FIELDS; ++j, ++p) {
            t.offA[p] = (unsigned short)((j * N_FIELDS + i) * QUADS);
            t.offC[p] = (unsigned short)((i * N_FIELDS + j) * QUADS);
        }
    return t;
}
__constant__ PairTab TAB = make_tab();

__global__ void __launch_bounds__(THREADS)
ffm_pair_kernel(const float4* __restrict__ in, float4* __restrict__ out)
{
    const int t0 = blockIdx.x * THREADS + threadIdx.x;

    int           idx[ILP];
    const float4* pa[ILP];
    const float4* pc[ILP];

    // Address generation first (ALU/LDC only), then batch all loads.
    #pragma unroll
    for (int k = 0; k < ILP; ++k) {
        int f4 = t0 + k * SPAN;          // exact grid: always < TOTAL_F4
        idx[k] = f4;
        int q  = f4 & (QUADS - 1);
        int bp = f4 >> 4;
        int p  = bp % NPAIRS;            // magic-mul
        int b  = bp / NPAIRS;
        const float4* base = in + (long)b * ROW_F4 + q;
        pa[k] = base + TAB.offA[p];
        pc[k] = base + TAB.offC[p];
    }

    float4 a[ILP], c[ILP];
    #pragma unroll
    for (int k = 0; k < ILP; ++k) a[k] = __ldcs(pa[k]);   // ld.global.cs (evict-first)
    #pragma unroll
    for (int k = 0; k < ILP; ++k) c[k] = __ldcs(pc[k]);

    #pragma unroll
    for (int k = 0; k < ILP; ++k) {
        float4 r;
        r.x = a[k].x * c[k].x;
        r.y = a[k].y * c[k].y;
        r.z = a[k].z * c[k].z;
        r.w = a[k].w * c[k].w;
        __stcs(&out[idx[k]], r);                          // st.global.cs (streaming)
    }
}

extern "C" void kernel_launch(void* const* d_in, const int* in_sizes, int n_in,
                              void* d_out, int out_size)
{
    const float4* in  = (const float4*)d_in[0];
    float4*       out = (float4*)d_out;
    ffm_pair_kernel<<<BLOCKS, THREADS>>>(in, out);
}